// round 16
// baseline (speedup 1.0000x reference)
#include <cuda_runtime.h>
#include <cuda_fp16.h>
#include <math.h>
#include <stdint.h>

#define D_MODEL   1024
#define N_HEADS   16
#define HEAD_DIM  64
#define SEQ_L     2048
#define BATCH     2
#define NTOK      (BATCH * SEQ_L)      // 4096
#define HALF_WIN  128                  // WINDOW//2
#define LN_EPS    1e-5f

// ---------------- scratch (no allocation allowed) ----------------
__device__ float  g_x1 [NTOK * D_MODEL];        // x + attn_out (fp32)
__device__ __half g_qkvh[NTOK * 3 * D_MODEL];   // qkv projection (fp16)
__device__ __half g_h16 [NTOK * D_MODEL];       // LN1 out, then reused for LN2 out
__device__ __half g_att16[NTOK * D_MODEL];      // attention output (fp16)
__device__ __half g_ff16 [NTOK * 2 * D_MODEL];  // gelu(ffn1) (fp16)
__device__ __half g_wq16 [D_MODEL * 3 * D_MODEL];
__device__ __half g_wo16 [D_MODEL * D_MODEL];
__device__ __half g_w116 [D_MODEL * 2 * D_MODEL];
__device__ __half g_w216 [2 * D_MODEL * D_MODEL];

// ---------------- helpers ----------------
__inline__ __device__ float warp_sum(float v) {
    #pragma unroll
    for (int o = 16; o > 0; o >>= 1) v += __shfl_xor_sync(0xffffffffu, v, o);
    return v;
}

__device__ __forceinline__ void cp16(void* smem_dst, const void* gmem_src) {
    uint32_t s = (uint32_t)__cvta_generic_to_shared(smem_dst);
    asm volatile("cp.async.cg.shared.global [%0], [%1], 16;\n" :: "r"(s), "l"(gmem_src));
}
__device__ __forceinline__ void cp_commit() { asm volatile("cp.async.commit_group;\n"); }
__device__ __forceinline__ void cp_wait0()  { asm volatile("cp.async.wait_group 0;\n"); }

__device__ __forceinline__ void mma_f16(float* c, const uint32_t* a, const uint32_t* b) {
    asm volatile(
        "mma.sync.aligned.m16n8k16.row.col.f32.f16.f16.f32 "
        "{%0,%1,%2,%3}, {%4,%5,%6,%7}, {%8,%9}, {%0,%1,%2,%3};\n"
        : "+f"(c[0]), "+f"(c[1]), "+f"(c[2]), "+f"(c[3])
        : "r"(a[0]), "r"(a[1]), "r"(a[2]), "r"(a[3]), "r"(b[0]), "r"(b[1]));
}
__device__ __forceinline__ void ldmx4(uint32_t& r0, uint32_t& r1, uint32_t& r2, uint32_t& r3, uint32_t addr) {
    asm volatile("ldmatrix.sync.aligned.m8n8.x4.shared.b16 {%0,%1,%2,%3}, [%4];\n"
                 : "=r"(r0), "=r"(r1), "=r"(r2), "=r"(r3) : "r"(addr));
}
__device__ __forceinline__ void ldmx4t(uint32_t& r0, uint32_t& r1, uint32_t& r2, uint32_t& r3, uint32_t addr) {
    asm volatile("ldmatrix.sync.aligned.m8n8.x4.trans.shared.b16 {%0,%1,%2,%3}, [%4];\n"
                 : "=r"(r0), "=r"(r1), "=r"(r2), "=r"(r3) : "r"(addr));
}
__device__ __forceinline__ uint32_t packh2(float a, float b) {
    __half2 t = __floats2half2_rn(a, b);
    return *(uint32_t*)&t;
}

// ---------------- fp32 -> fp16 weight conversion, single launch ----------------
#define N4_QKV (D_MODEL * 3 * D_MODEL / 4)
#define N4_OUT (D_MODEL * D_MODEL / 4)
#define N4_W1  (D_MODEL * 2 * D_MODEL / 4)
#define N4_W2  (2 * D_MODEL * D_MODEL / 4)
#define N4_ALL (N4_QKV + N4_OUT + N4_W1 + N4_W2)

__global__ void __launch_bounds__(256)
w2h_all_kernel(const float4* __restrict__ wq, const float4* __restrict__ wo,
               const float4* __restrict__ w1, const float4* __restrict__ w2,
               __half2* __restrict__ oq, __half2* __restrict__ oo,
               __half2* __restrict__ o1, __half2* __restrict__ o2)
{
    int i = blockIdx.x * 256 + threadIdx.x;
    if (i >= N4_ALL) return;
    const float4* src; __half2* dst; int k;
    if (i < N4_QKV)                       { src = wq; dst = oq; k = i; }
    else if (i < N4_QKV + N4_OUT)         { src = wo; dst = oo; k = i - N4_QKV; }
    else if (i < N4_QKV + N4_OUT + N4_W1) { src = w1; dst = o1; k = i - N4_QKV - N4_OUT; }
    else                                  { src = w2; dst = o2; k = i - N4_QKV - N4_OUT - N4_W1; }
    float4 v = src[k];
    dst[2 * k]     = __floats2half2_rn(v.x, v.y);
    dst[2 * k + 1] = __floats2half2_rn(v.z, v.w);
}

// ---------------- LayerNorm: one block per token, fp16 output ----------------
__global__ void __launch_bounds__(256)
ln_kernel(const float* __restrict__ x, const float* __restrict__ g,
          const float* __restrict__ b, __half* __restrict__ out)
{
    int row = blockIdx.x;
    const float* xr = x + (size_t)row * D_MODEL;
    __half*      orow = out + (size_t)row * D_MODEL;
    int tid = threadIdx.x;

    float v[4];
    float s = 0.f, ss = 0.f;
    #pragma unroll
    for (int i = 0; i < 4; i++) {
        v[i] = xr[tid + i * 256];
        s  += v[i];
        ss += v[i] * v[i];
    }
    __shared__ float shs[8], shss[8], fin[2];
    int lane = tid & 31, warp = tid >> 5;
    s = warp_sum(s); ss = warp_sum(ss);
    if (lane == 0) { shs[warp] = s; shss[warp] = ss; }
    __syncthreads();
    if (tid == 0) {
        float a = 0.f, c = 0.f;
        #pragma unroll
        for (int i = 0; i < 8; i++) { a += shs[i]; c += shss[i]; }
        fin[0] = a; fin[1] = c;
    }
    __syncthreads();
    float mu  = fin[0] * (1.f / D_MODEL);
    float var = fin[1] * (1.f / D_MODEL) - mu * mu;
    float inv = rsqrtf(var + LN_EPS);
    #pragma unroll
    for (int i = 0; i < 4; i++) {
        int c = tid + i * 256;
        orow[c] = __float2half_rn((v[i] - mu) * inv * g[c] + b[c]);
    }
}

// =================================================================
//  fp16 tensor-core GEMM (unchanged from R9): BK=64, 2-stage cp.async
// =================================================================
#define EPI_BIAS     0
#define EPI_BIAS_RES 1
#define EPI_GELU_H   2
#define EPI_BIAS_H   3

#define AP16 72
#define BP16 136
#define HASZ (128 * AP16)
#define HBSZ (64  * BP16)
#define GEMM_SMEM ((size_t)2 * (HASZ + HBSZ) * sizeof(__half))   // 71680 B

__global__ void __launch_bounds__(256)
gemm_h_kernel(const __half* __restrict__ A, const __half* __restrict__ Bm,
              const float* __restrict__ bias, const float* __restrict__ res,
              float* __restrict__ C, __half* __restrict__ Ch,
              int M, int N, int K, int epi)
{
    extern __shared__ __half hsm[];
    __half* As = hsm;
    __half* Bs = hsm + 2 * HASZ;
    uint32_t smem_u = (uint32_t)__cvta_generic_to_shared(hsm);

    int tid  = threadIdx.x;
    int lane = tid & 31;
    int warp = tid >> 5;
    int warp_m = (warp & 3) * 32;
    int warp_n = (warp >> 2) * 64;
    int bm = blockIdx.y * 128;
    int bn = blockIdx.x * 128;

    const int kIters = K >> 6;

    auto load_tile = [&](int it, int buf) {
        int k0 = it << 6;
        __half* Ab = As + buf * HASZ;
        __half* Bb = Bs + buf * HBSZ;
        #pragma unroll
        for (int t = 0; t < 4; t++) {
            int idx = tid + t * 256;
            int m  = idx >> 3;
            int c8 = (idx & 7) << 3;
            cp16(Ab + m * AP16 + c8, A + (size_t)(bm + m) * K + k0 + c8);
        }
        #pragma unroll
        for (int t = 0; t < 4; t++) {
            int idx = tid + t * 256;
            int k  = idx >> 4;
            int n8 = (idx & 15) << 3;
            cp16(Bb + k * BP16 + n8, Bm + (size_t)(k0 + k) * N + bn + n8);
        }
        cp_commit();
    };

    float acc[2][8][4];
    #pragma unroll
    for (int mt = 0; mt < 2; mt++)
        #pragma unroll
        for (int nt = 0; nt < 8; nt++)
            #pragma unroll
            for (int i = 0; i < 4; i++) acc[mt][nt][i] = 0.f;

    int a_row = warp_m + (lane & 15);
    int a_c8  = (lane >> 4) << 3;
    int b_k   = lane & 15;
    int b_c8  = (lane >> 4) << 3;

    load_tile(0, 0);

    int cur = 0;
    for (int it = 0; it < kIters; ++it) {
        cp_wait0();
        __syncthreads();
        if (it + 1 < kIters) load_tile(it + 1, cur ^ 1);

        uint32_t Abase = smem_u + (uint32_t)(cur * HASZ) * 2;
        uint32_t Bbase = smem_u + (uint32_t)(2 * HASZ + cur * HBSZ) * 2;

        #pragma unroll
        for (int kk = 0; kk < 4; ++kk) {
            uint32_t af[2][4], bf[8][2];
            #pragma unroll
            for (int mt = 0; mt < 2; mt++) {
                uint32_t addr = Abase + ((a_row + mt * 16) * AP16 + kk * 16 + a_c8) * 2;
                ldmx4(af[mt][0], af[mt][1], af[mt][2], af[mt][3], addr);
            }
            #pragma unroll
            for (int np = 0; np < 4; np++) {
                uint32_t addr = Bbase + ((kk * 16 + b_k) * BP16 + warp_n + np * 16 + b_c8) * 2;
                ldmx4t(bf[2 * np][0], bf[2 * np][1], bf[2 * np + 1][0], bf[2 * np + 1][1], addr);
            }
            #pragma unroll
            for (int mt = 0; mt < 2; mt++)
                #pragma unroll
                for (int nt = 0; nt < 8; nt++)
                    mma_f16(acc[mt][nt], af[mt], bf[nt]);
        }
        cur ^= 1;
    }

    #pragma unroll
    for (int mt = 0; mt < 2; mt++) {
        int row0 = bm + warp_m + mt * 16 + (lane >> 2);
        #pragma unroll
        for (int nt = 0; nt < 8; nt++) {
            int col = bn + warp_n + nt * 8 + (lane & 3) * 2;
            float b0 = bias[col], b1 = bias[col + 1];
            #pragma unroll
            for (int half_ = 0; half_ < 2; half_++) {
                int r = row0 + half_ * 8;
                float v0 = acc[mt][nt][half_ * 2 + 0] + b0;
                float v1 = acc[mt][nt][half_ * 2 + 1] + b1;
                if (epi == EPI_BIAS_RES) {
                    const float* rr = res + (size_t)r * N;
                    v0 += rr[col]; v1 += rr[col + 1];
                    *(float2*)(C + (size_t)r * N + col) = make_float2(v0, v1);
                } else if (epi == EPI_GELU_H) {
                    v0 = 0.5f * v0 * (1.0f + erff(v0 * 0.70710678118654752f));
                    v1 = 0.5f * v1 * (1.0f + erff(v1 * 0.70710678118654752f));
                    *(__half2*)(Ch + (size_t)r * N + col) = __floats2half2_rn(v0, v1);
                } else if (epi == EPI_BIAS_H) {
                    *(__half2*)(Ch + (size_t)r * N + col) = __floats2half2_rn(v0, v1);
                } else {
                    *(float2*)(C + (size_t)r * N + col) = make_float2(v0, v1);
                }
            }
        }
    }
}

// =================================================================
//  flash-style windowed attention: S and P stay in registers,
//  online softmax, split-KV across 2 warp groups, final merge.
//  grid (L/64, H, B), 256 threads. Warp w: rows (w&3)*16; group w>>2.
//  Group 0: k-tiles {0,2,4}; group 1: {1,3}.
// =================================================================
#define QP 72   // smem pitch in halves (144B row stride)

// smem half-offsets
#define SM_Q   0
#define SM_K0  4608
#define SM_V0  9216
#define SM_K1  13824
#define SM_V1  18432
#define SM_TOT 23040          // 46080 B static
// merge region aliases K1/V1 (group 1 done with them by then)
#define SM_O1F 13824          // float[64][68] = 17408 B
#define SM_M1  22528          // float[64]
#define SM_S1  22656          // float[64]  (half-offset; 22528*2+256 = 45312 B)

__global__ void __launch_bounds__(256, 2)
attn_flash_kernel(const __half* __restrict__ qkv, __half* __restrict__ attn)
{
    const int qt = blockIdx.x;
    const int h  = blockIdx.y;
    const int b  = blockIdx.z;
    const int q0 = qt * 64;
    const int j0 = q0 - HALF_WIN;

    __shared__ __half sm[SM_TOT];
    uint32_t su = (uint32_t)__cvta_generic_to_shared(sm);

    const int tid = threadIdx.x;
    const int lane = tid & 31, warp = tid >> 5;
    const int grp = warp >> 2;           // 0 or 1
    const int mw  = warp & 3;            // 16-row slice
    const int lr = lane >> 2, lc = lane & 3;
    const int l15 = lane & 15, lhi8 = (lane >> 4) << 3;
    const int gtid = tid & 127;

    const size_t base = (size_t)(b * SEQ_L) * 3072 + (size_t)h * 64;

    __half* Kg = sm + (grp ? SM_K1 : SM_K0);
    __half* Vg = sm + (grp ? SM_V1 : SM_V0);
    uint32_t Qu = su;
    uint32_t Ku = su + (grp ? SM_K1 : SM_K0) * 2;
    uint32_t Vu = su + (grp ? SM_V1 : SM_V0) * 2;

    // ---- load Q tile (all threads) ----
    #pragma unroll
    for (int t = 0; t < 2; ++t) {
        int idx = tid + t * 256;
        int r = idx >> 3, c8 = (idx & 7) << 3;
        *(uint4*)(sm + SM_Q + r * QP + c8) =
            *(const uint4*)(qkv + base + (size_t)(q0 + r) * 3072 + c8);
    }
    __syncthreads();

    // ---- Q fragments to registers (reused across all tiles) ----
    uint32_t qf[4][4];
    #pragma unroll
    for (int kk = 0; kk < 4; ++kk)
        ldmx4(qf[kk][0], qf[kk][1], qf[kk][2], qf[kk][3],
              Qu + ((mw * 16 + l15) * QP + kk * 16 + lhi8) * 2);

    float oacc[8][4];
    #pragma unroll
    for (int nt = 0; nt < 8; nt++)
        #pragma unroll
        for (int e = 0; e < 4; e++) oacc[nt][e] = 0.f;
    float m_run[2] = {-1e30f, -1e30f};
    float s_run[2] = {0.f, 0.f};

    const int ntile = grp ? 2 : 3;
    for (int tt = 0; tt < ntile; ++tt) {
        const int t = grp + tt * 2;
        const int jb = j0 + t * 64;

        if (tt) asm volatile("bar.sync %0, 128;" :: "r"(1 + grp));  // reads of prev tile done
        // ---- load K,V tile with the group's 128 threads ----
        #pragma unroll
        for (int u = 0; u < 4; ++u) {
            int idx = gtid + u * 128;
            int r = idx >> 3, c8 = (idx & 7) << 3;
            int j = jb + r; j = min(max(j, 0), SEQ_L - 1);
            const __half* src = qkv + base + (size_t)j * 3072;
            *(uint4*)(Kg + r * QP + c8) = *(const uint4*)(src + 1024 + c8);
            *(uint4*)(Vg + r * QP + c8) = *(const uint4*)(src + 2048 + c8);
        }
        asm volatile("bar.sync %0, 128;" :: "r"(1 + grp));

        // ---- S = Q @ K^T (16 x 64 per warp, in registers) ----
        float sacc[8][4];
        #pragma unroll
        for (int nt = 0; nt < 8; nt++)
            #pragma unroll
            for (int e = 0; e < 4; e++) sacc[nt][e] = 0.f;
        #pragma unroll
        for (int kk = 0; kk < 4; ++kk) {
            uint32_t bf[8][2];
            #pragma unroll
            for (int np = 0; np < 4; ++np) {
                uint32_t r0, r1, r2, r3;
                ldmx4(r0, r1, r2, r3, Ku + ((np * 16 + l15) * QP + kk * 16 + lhi8) * 2);
                bf[2 * np][0] = r0; bf[2 * np][1] = r2;
                bf[2 * np + 1][0] = r1; bf[2 * np + 1][1] = r3;
            }
            #pragma unroll
            for (int nt = 0; nt < 8; ++nt) mma_f16(sacc[nt], qf[kk], bf[nt]);
        }

        // ---- mask + scale + tile max ----
        float mt[2] = {-INFINITY, -INFINITY};
        #pragma unroll
        for (int nt = 0; nt < 8; ++nt) {
            #pragma unroll
            for (int e = 0; e < 4; ++e) {
                int rl = mw * 16 + lr + (e >> 1) * 8;
                int cl = nt * 8 + 2 * lc + (e & 1);
                int j  = jb + cl;
                int d  = j - (q0 + rl);
                bool ok = (j >= 0) && (j < SEQ_L) && (d >= -HALF_WIN) && (d <= HALF_WIN);
                float v = ok ? sacc[nt][e] * 0.125f : -INFINITY;
                sacc[nt][e] = v;
                mt[e >> 1] = fmaxf(mt[e >> 1], v);
            }
        }
        #pragma unroll
        for (int o = 1; o <= 2; o <<= 1) {
            mt[0] = fmaxf(mt[0], __shfl_xor_sync(0xffffffffu, mt[0], o));
            mt[1] = fmaxf(mt[1], __shfl_xor_sync(0xffffffffu, mt[1], o));
        }

        float nm[2], f[2];
        #pragma unroll
        for (int rr = 0; rr < 2; ++rr) {
            nm[rr] = fmaxf(fmaxf(m_run[rr], mt[rr]), -1e30f);
            f[rr]  = __expf(m_run[rr] - nm[rr]);
            m_run[rr] = nm[rr];
        }

        // ---- P = exp(S - m) in registers -> fp16 A-fragments; row sums ----
        uint32_t pa[4][4];
        float sum_t[2] = {0.f, 0.f};
        #pragma unroll
        for (int nt = 0; nt < 8; ++nt) {
            float p0 = __expf(sacc[nt][0] - nm[0]);
            float p1 = __expf(sacc[nt][1] - nm[0]);
            float p2 = __expf(sacc[nt][2] - nm[1]);
            float p3 = __expf(sacc[nt][3] - nm[1]);
            sum_t[0] += p0 + p1;
            sum_t[1] += p2 + p3;
            int kk = nt >> 1;
            if ((nt & 1) == 0) {
                pa[kk][0] = packh2(p0, p1);
                pa[kk][1] = packh2(p2, p3);
            } else {
                pa[kk][2] = packh2(p0, p1);
                pa[kk][3] = packh2(p2, p3);
            }
        }
        #pragma unroll
        for (int o = 1; o <= 2; o <<= 1) {
            sum_t[0] += __shfl_xor_sync(0xffffffffu, sum_t[0], o);
            sum_t[1] += __shfl_xor_sync(0xffffffffu, sum_t[1], o);
        }
        s_run[0] = s_run[0] * f[0] + sum_t[0];
        s_run[1] = s_run[1] * f[1] + sum_t[1];

        // ---- rescale O, then O += P @ V ----
        #pragma unroll
        for (int nt = 0; nt < 8; ++nt) {
            oacc[nt][0] *= f[0]; oacc[nt][1] *= f[0];
            oacc[nt][2] *= f[1]; oacc[nt][3] *= f[1];
        }
        #pragma unroll
        for (int kk = 0; kk < 4; ++kk) {
            uint32_t bf[8][2];
            #pragma unroll
            for (int np = 0; np < 4; ++np)
                ldmx4t(bf[2 * np][0], bf[2 * np][1], bf[2 * np + 1][0], bf[2 * np + 1][1],
                       Vu + ((kk * 16 + l15) * QP + np * 16 + lhi8) * 2);
            #pragma unroll
            for (int nt = 0; nt < 8; ++nt) mma_f16(oacc[nt], pa[kk], bf[nt]);
        }
    }

    // ---- merge the two split-KV partials ----
    float* O1s = (float*)(sm + SM_O1F);   // [64][68]
    float* m1s = (float*)(sm + SM_M1);    // [64]
    float* s1s = (float*)(sm + SM_S1);    // [64]

    if (grp == 1) {
        // all group-1 warps must be done reading K1/V1 before aliasing them
        asm volatile("bar.sync 2, 128;");
        #pragma unroll
        for (int nt = 0; nt < 8; ++nt) {
            #pragma unroll
            for (int e = 0; e < 4; ++e) {
                int row = mw * 16 + lr + (e >> 1) * 8;
                int col = nt * 8 + 2 * lc + (e & 1);
                O1s[row * 68 + col] = oacc[nt][e];
            }
        }
        if (lc == 0) {
            int r0 = mw * 16 + lr;
            m1s[r0] = m_run[0]; s1s[r0] = s_run[0];
            m1s[r0 + 8] = m_run[1]; s1s[r0 + 8] = s_run[1];
        }
    }
    __syncthreads();

    if (grp == 0) {
        int r0 = mw * 16 + lr;
        int r1 = r0 + 8;
        float m1a = m1s[r0], s1a = s1s[r0];
        float m1b = m1s[r1], s1b = s1s[r1];
        float M0 = fmaxf(m_run[0], m1a);
        float M1 = fmaxf(m_run[1], m1b);
        float w00 = __expf(m_run[0] - M0), w01 = __expf(m1a - M0);
        float w10 = __expf(m_run[1] - M1), w11 = __expf(m1b - M1);
        float inv0 = 1.f / (s_run[0] * w00 + s1a * w01);
        float inv1 = 1.f / (s_run[1] * w10 + s1b * w11);
        #pragma unroll
        for (int nt = 0; nt < 8; ++nt) {
            int coll = nt * 8 + 2 * lc;
            float v0 = (oacc[nt][0] * w00 + O1s[r0 * 68 + coll]     * w01) * inv0;
            float v1 = (oacc[nt][1] * w00 + O1s[r0 * 68 + coll + 1] * w01) * inv0;
            float v2 = (oacc[nt][2] * w10 + O1s[r1 * 68 + coll]     * w11) * inv1;
            float v3 = (oacc[nt][3] * w10 + O1s[r1 * 68 + coll + 1] * w11) * inv1;
            int gcol = h * 64 + coll;
            *(__half2*)(attn + (size_t)(b * SEQ_L + q0 + r0) * D_MODEL + gcol) = __floats2half2_rn(v0, v1);
            *(__half2*)(attn + (size_t)(b * SEQ_L + q0 + r1) * D_MODEL + gcol) = __floats2half2_rn(v2, v3);
        }
    }
}

// ---------------- launch ----------------
extern "C" void kernel_launch(void* const* d_in, const int* in_sizes, int n_in,
                              void* d_out, int out_size)
{
    const float* x      = (const float*)d_in[0];
    const float* qkv_w  = (const float*)d_in[1];
    const float* qkv_b  = (const float*)d_in[2];
    const float* out_w  = (const float*)d_in[3];
    const float* out_b  = (const float*)d_in[4];
    const float* ln1_g  = (const float*)d_in[5];
    const float* ln1_b  = (const float*)d_in[6];
    const float* ln2_g  = (const float*)d_in[7];
    const float* ln2_b  = (const float*)d_in[8];
    const float* ffn_w1 = (const float*)d_in[9];
    const float* ffn_b1 = (const float*)d_in[10];
    const float* ffn_w2 = (const float*)d_in[11];
    const float* ffn_b2 = (const float*)d_in[12];
    float* out = (float*)d_out;

    float *x1;
    __half *qkvh, *h16, *att16, *ff16, *wq16, *wo16, *w116, *w216;
    cudaGetSymbolAddress((void**)&x1,   g_x1);
    cudaGetSymbolAddress((void**)&qkvh, g_qkvh);
    cudaGetSymbolAddress((void**)&h16,  g_h16);
    cudaGetSymbolAddress((void**)&att16,g_att16);
    cudaGetSymbolAddress((void**)&ff16, g_ff16);
    cudaGetSymbolAddress((void**)&wq16, g_wq16);
    cudaGetSymbolAddress((void**)&wo16, g_wo16);
    cudaGetSymbolAddress((void**)&w116, g_w116);
    cudaGetSymbolAddress((void**)&w216, g_w216);

    cudaFuncSetAttribute(gemm_h_kernel, cudaFuncAttributeMaxDynamicSharedMemorySize, (int)GEMM_SMEM);

    // 0) all weight conversions fp32->fp16, one launch
    w2h_all_kernel<<<(N4_ALL + 255) / 256, 256>>>(
        (const float4*)qkv_w, (const float4*)out_w, (const float4*)ffn_w1, (const float4*)ffn_w2,
        (__half2*)wq16, (__half2*)wo16, (__half2*)w116, (__half2*)w216);

    // 1) LN1 -> fp16
    ln_kernel<<<NTOK, 256>>>(x, ln1_g, ln1_b, h16);
    // 2) QKV projection (fp16 TC, fp16 out)
    gemm_h_kernel<<<dim3(3 * D_MODEL / 128, NTOK / 128), 256, GEMM_SMEM>>>(
        h16, wq16, qkv_b, nullptr, nullptr, qkvh, NTOK, 3 * D_MODEL, D_MODEL, EPI_BIAS_H);
    // 3) flash windowed attention (fp16 TC)
    attn_flash_kernel<<<dim3(SEQ_L / 64, N_HEADS, BATCH), 256>>>(qkvh, att16);
    // 4) output projection + residual (fp16 TC, fp32 out)
    gemm_h_kernel<<<dim3(D_MODEL / 128, NTOK / 128), 256, GEMM_SMEM>>>(
        att16, wo16, out_b, x, x1, nullptr, NTOK, D_MODEL, D_MODEL, EPI_BIAS_RES);
    // 5) LN2 -> fp16
    ln_kernel<<<NTOK, 256>>>(x1, ln2_g, ln2_b, h16);
    // 6) FFN1 + GELU (fp16 TC, fp16 out)
    gemm_h_kernel<<<dim3(2 * D_MODEL / 128, NTOK / 128), 256, GEMM_SMEM>>>(
        h16, w116, ffn_b1, nullptr, nullptr, ff16, NTOK, 2 * D_MODEL, D_MODEL, EPI_GELU_H);
    // 7) FFN2 + residual -> out (fp16 TC, fp32 out)
    gemm_h_kernel<<<dim3(D_MODEL / 128, NTOK / 128), 256, GEMM_SMEM>>>(
        ff16, w216, ffn_b2, x1, out, nullptr, NTOK, D_MODEL, 2 * D_MODEL, EPI_BIAS_RES);
}

// round 17
// speedup vs baseline: 1.0018x; 1.0018x over previous
#include <cuda_runtime.h>
#include <cuda_fp16.h>
#include <math.h>
#include <stdint.h>

#define D_MODEL   1024
#define N_HEADS   16
#define HEAD_DIM  64
#define SEQ_L     2048
#define BATCH     2
#define NTOK      (BATCH * SEQ_L)      // 4096
#define HALF_WIN  128                  // WINDOW//2
#define LN_EPS    1e-5f

// ---------------- scratch (no allocation allowed) ----------------
__device__ float  g_x1 [NTOK * D_MODEL];        // x + attn_out (fp32)
__device__ __half g_qkvh[NTOK * 3 * D_MODEL];   // qkv projection (fp16)
__device__ __half g_h16 [NTOK * D_MODEL];       // LN1 out, then reused for LN2 out
__device__ __half g_att16[NTOK * D_MODEL];      // attention output (fp16)
__device__ __half g_ff16 [NTOK * 2 * D_MODEL];  // gelu(ffn1) (fp16)
__device__ __half g_wq16 [D_MODEL * 3 * D_MODEL];
__device__ __half g_wo16 [D_MODEL * D_MODEL];
__device__ __half g_w116 [D_MODEL * 2 * D_MODEL];
__device__ __half g_w216 [2 * D_MODEL * D_MODEL];

// ---------------- helpers ----------------
__inline__ __device__ float warp_sum(float v) {
    #pragma unroll
    for (int o = 16; o > 0; o >>= 1) v += __shfl_xor_sync(0xffffffffu, v, o);
    return v;
}

__device__ __forceinline__ void cp16(void* smem_dst, const void* gmem_src) {
    uint32_t s = (uint32_t)__cvta_generic_to_shared(smem_dst);
    asm volatile("cp.async.cg.shared.global [%0], [%1], 16;\n" :: "r"(s), "l"(gmem_src));
}
__device__ __forceinline__ void cp_commit() { asm volatile("cp.async.commit_group;\n"); }
__device__ __forceinline__ void cp_wait0()  { asm volatile("cp.async.wait_group 0;\n"); }

__device__ __forceinline__ void mma_f16(float* c, const uint32_t* a, const uint32_t* b) {
    asm volatile(
        "mma.sync.aligned.m16n8k16.row.col.f32.f16.f16.f32 "
        "{%0,%1,%2,%3}, {%4,%5,%6,%7}, {%8,%9}, {%0,%1,%2,%3};\n"
        : "+f"(c[0]), "+f"(c[1]), "+f"(c[2]), "+f"(c[3])
        : "r"(a[0]), "r"(a[1]), "r"(a[2]), "r"(a[3]), "r"(b[0]), "r"(b[1]));
}
__device__ __forceinline__ void ldmx4(uint32_t& r0, uint32_t& r1, uint32_t& r2, uint32_t& r3, uint32_t addr) {
    asm volatile("ldmatrix.sync.aligned.m8n8.x4.shared.b16 {%0,%1,%2,%3}, [%4];\n"
                 : "=r"(r0), "=r"(r1), "=r"(r2), "=r"(r3) : "r"(addr));
}
__device__ __forceinline__ void ldmx4t(uint32_t& r0, uint32_t& r1, uint32_t& r2, uint32_t& r3, uint32_t addr) {
    asm volatile("ldmatrix.sync.aligned.m8n8.x4.trans.shared.b16 {%0,%1,%2,%3}, [%4];\n"
                 : "=r"(r0), "=r"(r1), "=r"(r2), "=r"(r3) : "r"(addr));
}
__device__ __forceinline__ uint32_t packh2(float a, float b) {
    __half2 t = __floats2half2_rn(a, b);
    return *(uint32_t*)&t;
}

// ---------------- fp32 -> fp16 weight conversion, single launch ----------------
#define N4_QKV (D_MODEL * 3 * D_MODEL / 4)
#define N4_OUT (D_MODEL * D_MODEL / 4)
#define N4_W1  (D_MODEL * 2 * D_MODEL / 4)
#define N4_W2  (2 * D_MODEL * D_MODEL / 4)
#define N4_ALL (N4_QKV + N4_OUT + N4_W1 + N4_W2)

__global__ void __launch_bounds__(256)
w2h_all_kernel(const float4* __restrict__ wq, const float4* __restrict__ wo,
               const float4* __restrict__ w1, const float4* __restrict__ w2,
               __half2* __restrict__ oq, __half2* __restrict__ oo,
               __half2* __restrict__ o1, __half2* __restrict__ o2)
{
    int i = blockIdx.x * 256 + threadIdx.x;
    if (i >= N4_ALL) return;
    const float4* src; __half2* dst; int k;
    if (i < N4_QKV)                       { src = wq; dst = oq; k = i; }
    else if (i < N4_QKV + N4_OUT)         { src = wo; dst = oo; k = i - N4_QKV; }
    else if (i < N4_QKV + N4_OUT + N4_W1) { src = w1; dst = o1; k = i - N4_QKV - N4_OUT; }
    else                                  { src = w2; dst = o2; k = i - N4_QKV - N4_OUT - N4_W1; }
    float4 v = src[k];
    dst[2 * k]     = __floats2half2_rn(v.x, v.y);
    dst[2 * k + 1] = __floats2half2_rn(v.z, v.w);
}

// ---------------- LayerNorm: one block per token, fp16 output ----------------
__global__ void __launch_bounds__(256)
ln_kernel(const float* __restrict__ x, const float* __restrict__ g,
          const float* __restrict__ b, __half* __restrict__ out)
{
    int row = blockIdx.x;
    const float* xr = x + (size_t)row * D_MODEL;
    __half*      orow = out + (size_t)row * D_MODEL;
    int tid = threadIdx.x;

    float v[4];
    float s = 0.f, ss = 0.f;
    #pragma unroll
    for (int i = 0; i < 4; i++) {
        v[i] = xr[tid + i * 256];
        s  += v[i];
        ss += v[i] * v[i];
    }
    __shared__ float shs[8], shss[8], fin[2];
    int lane = tid & 31, warp = tid >> 5;
    s = warp_sum(s); ss = warp_sum(ss);
    if (lane == 0) { shs[warp] = s; shss[warp] = ss; }
    __syncthreads();
    if (tid == 0) {
        float a = 0.f, c = 0.f;
        #pragma unroll
        for (int i = 0; i < 8; i++) { a += shs[i]; c += shss[i]; }
        fin[0] = a; fin[1] = c;
    }
    __syncthreads();
    float mu  = fin[0] * (1.f / D_MODEL);
    float var = fin[1] * (1.f / D_MODEL) - mu * mu;
    float inv = rsqrtf(var + LN_EPS);
    #pragma unroll
    for (int i = 0; i < 4; i++) {
        int c = tid + i * 256;
        orow[c] = __float2half_rn((v[i] - mu) * inv * g[c] + b[c]);
    }
}

// =================================================================
//  fp16 tensor-core GEMM (unchanged from R9): BK=64, 2-stage cp.async
// =================================================================
#define EPI_BIAS     0
#define EPI_BIAS_RES 1
#define EPI_GELU_H   2
#define EPI_BIAS_H   3

#define AP16 72
#define BP16 136
#define HASZ (128 * AP16)
#define HBSZ (64  * BP16)
#define GEMM_SMEM ((size_t)2 * (HASZ + HBSZ) * sizeof(__half))   // 71680 B

__global__ void __launch_bounds__(256)
gemm_h_kernel(const __half* __restrict__ A, const __half* __restrict__ Bm,
              const float* __restrict__ bias, const float* __restrict__ res,
              float* __restrict__ C, __half* __restrict__ Ch,
              int M, int N, int K, int epi)
{
    extern __shared__ __half hsm[];
    __half* As = hsm;
    __half* Bs = hsm + 2 * HASZ;
    uint32_t smem_u = (uint32_t)__cvta_generic_to_shared(hsm);

    int tid  = threadIdx.x;
    int lane = tid & 31;
    int warp = tid >> 5;
    int warp_m = (warp & 3) * 32;
    int warp_n = (warp >> 2) * 64;
    int bm = blockIdx.y * 128;
    int bn = blockIdx.x * 128;

    const int kIters = K >> 6;

    auto load_tile = [&](int it, int buf) {
        int k0 = it << 6;
        __half* Ab = As + buf * HASZ;
        __half* Bb = Bs + buf * HBSZ;
        #pragma unroll
        for (int t = 0; t < 4; t++) {
            int idx = tid + t * 256;
            int m  = idx >> 3;
            int c8 = (idx & 7) << 3;
            cp16(Ab + m * AP16 + c8, A + (size_t)(bm + m) * K + k0 + c8);
        }
        #pragma unroll
        for (int t = 0; t < 4; t++) {
            int idx = tid + t * 256;
            int k  = idx >> 4;
            int n8 = (idx & 15) << 3;
            cp16(Bb + k * BP16 + n8, Bm + (size_t)(k0 + k) * N + bn + n8);
        }
        cp_commit();
    };

    float acc[2][8][4];
    #pragma unroll
    for (int mt = 0; mt < 2; mt++)
        #pragma unroll
        for (int nt = 0; nt < 8; nt++)
            #pragma unroll
            for (int i = 0; i < 4; i++) acc[mt][nt][i] = 0.f;

    int a_row = warp_m + (lane & 15);
    int a_c8  = (lane >> 4) << 3;
    int b_k   = lane & 15;
    int b_c8  = (lane >> 4) << 3;

    load_tile(0, 0);

    int cur = 0;
    for (int it = 0; it < kIters; ++it) {
        cp_wait0();
        __syncthreads();
        if (it + 1 < kIters) load_tile(it + 1, cur ^ 1);

        uint32_t Abase = smem_u + (uint32_t)(cur * HASZ) * 2;
        uint32_t Bbase = smem_u + (uint32_t)(2 * HASZ + cur * HBSZ) * 2;

        #pragma unroll
        for (int kk = 0; kk < 4; ++kk) {
            uint32_t af[2][4], bf[8][2];
            #pragma unroll
            for (int mt = 0; mt < 2; mt++) {
                uint32_t addr = Abase + ((a_row + mt * 16) * AP16 + kk * 16 + a_c8) * 2;
                ldmx4(af[mt][0], af[mt][1], af[mt][2], af[mt][3], addr);
            }
            #pragma unroll
            for (int np = 0; np < 4; np++) {
                uint32_t addr = Bbase + ((kk * 16 + b_k) * BP16 + warp_n + np * 16 + b_c8) * 2;
                ldmx4t(bf[2 * np][0], bf[2 * np][1], bf[2 * np + 1][0], bf[2 * np + 1][1], addr);
            }
            #pragma unroll
            for (int mt = 0; mt < 2; mt++)
                #pragma unroll
                for (int nt = 0; nt < 8; nt++)
                    mma_f16(acc[mt][nt], af[mt], bf[nt]);
        }
        cur ^= 1;
    }

    #pragma unroll
    for (int mt = 0; mt < 2; mt++) {
        int row0 = bm + warp_m + mt * 16 + (lane >> 2);
        #pragma unroll
        for (int nt = 0; nt < 8; nt++) {
            int col = bn + warp_n + nt * 8 + (lane & 3) * 2;
            float b0 = bias[col], b1 = bias[col + 1];
            #pragma unroll
            for (int half_ = 0; half_ < 2; half_++) {
                int r = row0 + half_ * 8;
                float v0 = acc[mt][nt][half_ * 2 + 0] + b0;
                float v1 = acc[mt][nt][half_ * 2 + 1] + b1;
                if (epi == EPI_BIAS_RES) {
                    const float* rr = res + (size_t)r * N;
                    v0 += rr[col]; v1 += rr[col + 1];
                    *(float2*)(C + (size_t)r * N + col) = make_float2(v0, v1);
                } else if (epi == EPI_GELU_H) {
                    v0 = 0.5f * v0 * (1.0f + erff(v0 * 0.70710678118654752f));
                    v1 = 0.5f * v1 * (1.0f + erff(v1 * 0.70710678118654752f));
                    *(__half2*)(Ch + (size_t)r * N + col) = __floats2half2_rn(v0, v1);
                } else if (epi == EPI_BIAS_H) {
                    *(__half2*)(Ch + (size_t)r * N + col) = __floats2half2_rn(v0, v1);
                } else {
                    *(float2*)(C + (size_t)r * N + col) = make_float2(v0, v1);
                }
            }
        }
    }
}

// =================================================================
//  flash-style windowed attention: S and P stay in registers,
//  online softmax, split-KV across 2 warp groups, final merge.
//  grid (L/64, H, B), 256 threads. Warp w: rows (w&3)*16; group w>>2.
//  Group 0: k-tiles {0,2,4}; group 1: {1,3}.
// =================================================================
#define QP 72   // smem pitch in halves (144B row stride)

// smem half-offsets
#define SM_Q   0
#define SM_K0  4608
#define SM_V0  9216
#define SM_K1  13824
#define SM_V1  18432
#define SM_TOT 23040          // 46080 B static
// merge region aliases K1/V1 (group 1 done with them by then)
#define SM_O1F 13824          // float[64][68] = 17408 B
#define SM_M1  22528          // float[64]
#define SM_S1  22656          // float[64]  (half-offset; 22528*2+256 = 45312 B)

__global__ void __launch_bounds__(256, 2)
attn_flash_kernel(const __half* __restrict__ qkv, __half* __restrict__ attn)
{
    const int qt = blockIdx.x;
    const int h  = blockIdx.y;
    const int b  = blockIdx.z;
    const int q0 = qt * 64;
    const int j0 = q0 - HALF_WIN;

    __shared__ __half sm[SM_TOT];
    uint32_t su = (uint32_t)__cvta_generic_to_shared(sm);

    const int tid = threadIdx.x;
    const int lane = tid & 31, warp = tid >> 5;
    const int grp = warp >> 2;           // 0 or 1
    const int mw  = warp & 3;            // 16-row slice
    const int lr = lane >> 2, lc = lane & 3;
    const int l15 = lane & 15, lhi8 = (lane >> 4) << 3;
    const int gtid = tid & 127;

    const size_t base = (size_t)(b * SEQ_L) * 3072 + (size_t)h * 64;

    __half* Kg = sm + (grp ? SM_K1 : SM_K0);
    __half* Vg = sm + (grp ? SM_V1 : SM_V0);
    uint32_t Qu = su;
    uint32_t Ku = su + (grp ? SM_K1 : SM_K0) * 2;
    uint32_t Vu = su + (grp ? SM_V1 : SM_V0) * 2;

    // ---- load Q tile (all threads) ----
    #pragma unroll
    for (int t = 0; t < 2; ++t) {
        int idx = tid + t * 256;
        int r = idx >> 3, c8 = (idx & 7) << 3;
        *(uint4*)(sm + SM_Q + r * QP + c8) =
            *(const uint4*)(qkv + base + (size_t)(q0 + r) * 3072 + c8);
    }
    __syncthreads();

    // ---- Q fragments to registers (reused across all tiles) ----
    uint32_t qf[4][4];
    #pragma unroll
    for (int kk = 0; kk < 4; ++kk)
        ldmx4(qf[kk][0], qf[kk][1], qf[kk][2], qf[kk][3],
              Qu + ((mw * 16 + l15) * QP + kk * 16 + lhi8) * 2);

    float oacc[8][4];
    #pragma unroll
    for (int nt = 0; nt < 8; nt++)
        #pragma unroll
        for (int e = 0; e < 4; e++) oacc[nt][e] = 0.f;
    float m_run[2] = {-1e30f, -1e30f};
    float s_run[2] = {0.f, 0.f};

    const int ntile = grp ? 2 : 3;
    for (int tt = 0; tt < ntile; ++tt) {
        const int t = grp + tt * 2;
        const int jb = j0 + t * 64;

        if (tt) asm volatile("bar.sync %0, 128;" :: "r"(1 + grp));  // reads of prev tile done
        // ---- load K,V tile with the group's 128 threads ----
        #pragma unroll
        for (int u = 0; u < 4; ++u) {
            int idx = gtid + u * 128;
            int r = idx >> 3, c8 = (idx & 7) << 3;
            int j = jb + r; j = min(max(j, 0), SEQ_L - 1);
            const __half* src = qkv + base + (size_t)j * 3072;
            *(uint4*)(Kg + r * QP + c8) = *(const uint4*)(src + 1024 + c8);
            *(uint4*)(Vg + r * QP + c8) = *(const uint4*)(src + 2048 + c8);
        }
        asm volatile("bar.sync %0, 128;" :: "r"(1 + grp));

        // ---- S = Q @ K^T (16 x 64 per warp, in registers) ----
        float sacc[8][4];
        #pragma unroll
        for (int nt = 0; nt < 8; nt++)
            #pragma unroll
            for (int e = 0; e < 4; e++) sacc[nt][e] = 0.f;
        #pragma unroll
        for (int kk = 0; kk < 4; ++kk) {
            uint32_t bf[8][2];
            #pragma unroll
            for (int np = 0; np < 4; ++np) {
                uint32_t r0, r1, r2, r3;
                ldmx4(r0, r1, r2, r3, Ku + ((np * 16 + l15) * QP + kk * 16 + lhi8) * 2);
                bf[2 * np][0] = r0; bf[2 * np][1] = r2;
                bf[2 * np + 1][0] = r1; bf[2 * np + 1][1] = r3;
            }
            #pragma unroll
            for (int nt = 0; nt < 8; ++nt) mma_f16(sacc[nt], qf[kk], bf[nt]);
        }

        // ---- mask + scale + tile max ----
        float mt[2] = {-INFINITY, -INFINITY};
        #pragma unroll
        for (int nt = 0; nt < 8; ++nt) {
            #pragma unroll
            for (int e = 0; e < 4; ++e) {
                int rl = mw * 16 + lr + (e >> 1) * 8;
                int cl = nt * 8 + 2 * lc + (e & 1);
                int j  = jb + cl;
                int d  = j - (q0 + rl);
                bool ok = (j >= 0) && (j < SEQ_L) && (d >= -HALF_WIN) && (d <= HALF_WIN);
                float v = ok ? sacc[nt][e] * 0.125f : -INFINITY;
                sacc[nt][e] = v;
                mt[e >> 1] = fmaxf(mt[e >> 1], v);
            }
        }
        #pragma unroll
        for (int o = 1; o <= 2; o <<= 1) {
            mt[0] = fmaxf(mt[0], __shfl_xor_sync(0xffffffffu, mt[0], o));
            mt[1] = fmaxf(mt[1], __shfl_xor_sync(0xffffffffu, mt[1], o));
        }

        float nm[2], f[2];
        #pragma unroll
        for (int rr = 0; rr < 2; ++rr) {
            nm[rr] = fmaxf(fmaxf(m_run[rr], mt[rr]), -1e30f);
            f[rr]  = __expf(m_run[rr] - nm[rr]);
            m_run[rr] = nm[rr];
        }

        // ---- P = exp(S - m) in registers -> fp16 A-fragments; row sums ----
        uint32_t pa[4][4];
        float sum_t[2] = {0.f, 0.f};
        #pragma unroll
        for (int nt = 0; nt < 8; ++nt) {
            float p0 = __expf(sacc[nt][0] - nm[0]);
            float p1 = __expf(sacc[nt][1] - nm[0]);
            float p2 = __expf(sacc[nt][2] - nm[1]);
            float p3 = __expf(sacc[nt][3] - nm[1]);
            sum_t[0] += p0 + p1;
            sum_t[1] += p2 + p3;
            int kk = nt >> 1;
            if ((nt & 1) == 0) {
                pa[kk][0] = packh2(p0, p1);
                pa[kk][1] = packh2(p2, p3);
            } else {
                pa[kk][2] = packh2(p0, p1);
                pa[kk][3] = packh2(p2, p3);
            }
        }
        #pragma unroll
        for (int o = 1; o <= 2; o <<= 1) {
            sum_t[0] += __shfl_xor_sync(0xffffffffu, sum_t[0], o);
            sum_t[1] += __shfl_xor_sync(0xffffffffu, sum_t[1], o);
        }
        s_run[0] = s_run[0] * f[0] + sum_t[0];
        s_run[1] = s_run[1] * f[1] + sum_t[1];

        // ---- rescale O, then O += P @ V ----
        #pragma unroll
        for (int nt = 0; nt < 8; ++nt) {
            oacc[nt][0] *= f[0]; oacc[nt][1] *= f[0];
            oacc[nt][2] *= f[1]; oacc[nt][3] *= f[1];
        }
        #pragma unroll
        for (int kk = 0; kk < 4; ++kk) {
            uint32_t bf[8][2];
            #pragma unroll
            for (int np = 0; np < 4; ++np)
                ldmx4t(bf[2 * np][0], bf[2 * np][1], bf[2 * np + 1][0], bf[2 * np + 1][1],
                       Vu + ((kk * 16 + l15) * QP + np * 16 + lhi8) * 2);
            #pragma unroll
            for (int nt = 0; nt < 8; ++nt) mma_f16(oacc[nt], pa[kk], bf[nt]);
        }
    }

    // ---- merge the two split-KV partials ----
    float* O1s = (float*)(sm + SM_O1F);   // [64][68]
    float* m1s = (float*)(sm + SM_M1);    // [64]
    float* s1s = (float*)(sm + SM_S1);    // [64]

    if (grp == 1) {
        // all group-1 warps must be done reading K1/V1 before aliasing them
        asm volatile("bar.sync 2, 128;");
        #pragma unroll
        for (int nt = 0; nt < 8; ++nt) {
            #pragma unroll
            for (int e = 0; e < 4; ++e) {
                int row = mw * 16 + lr + (e >> 1) * 8;
                int col = nt * 8 + 2 * lc + (e & 1);
                O1s[row * 68 + col] = oacc[nt][e];
            }
        }
        if (lc == 0) {
            int r0 = mw * 16 + lr;
            m1s[r0] = m_run[0]; s1s[r0] = s_run[0];
            m1s[r0 + 8] = m_run[1]; s1s[r0 + 8] = s_run[1];
        }
    }
    __syncthreads();

    if (grp == 0) {
        int r0 = mw * 16 + lr;
        int r1 = r0 + 8;
        float m1a = m1s[r0], s1a = s1s[r0];
        float m1b = m1s[r1], s1b = s1s[r1];
        float M0 = fmaxf(m_run[0], m1a);
        float M1 = fmaxf(m_run[1], m1b);
        float w00 = __expf(m_run[0] - M0), w01 = __expf(m1a - M0);
        float w10 = __expf(m_run[1] - M1), w11 = __expf(m1b - M1);
        float inv0 = 1.f / (s_run[0] * w00 + s1a * w01);
        float inv1 = 1.f / (s_run[1] * w10 + s1b * w11);
        #pragma unroll
        for (int nt = 0; nt < 8; ++nt) {
            int coll = nt * 8 + 2 * lc;
            float v0 = (oacc[nt][0] * w00 + O1s[r0 * 68 + coll]     * w01) * inv0;
            float v1 = (oacc[nt][1] * w00 + O1s[r0 * 68 + coll + 1] * w01) * inv0;
            float v2 = (oacc[nt][2] * w10 + O1s[r1 * 68 + coll]     * w11) * inv1;
            float v3 = (oacc[nt][3] * w10 + O1s[r1 * 68 + coll + 1] * w11) * inv1;
            int gcol = h * 64 + coll;
            *(__half2*)(attn + (size_t)(b * SEQ_L + q0 + r0) * D_MODEL + gcol) = __floats2half2_rn(v0, v1);
            *(__half2*)(attn + (size_t)(b * SEQ_L + q0 + r1) * D_MODEL + gcol) = __floats2half2_rn(v2, v3);
        }
    }
}

// ---------------- launch ----------------
extern "C" void kernel_launch(void* const* d_in, const int* in_sizes, int n_in,
                              void* d_out, int out_size)
{
    const float* x      = (const float*)d_in[0];
    const float* qkv_w  = (const float*)d_in[1];
    const float* qkv_b  = (const float*)d_in[2];
    const float* out_w  = (const float*)d_in[3];
    const float* out_b  = (const float*)d_in[4];
    const float* ln1_g  = (const float*)d_in[5];
    const float* ln1_b  = (const float*)d_in[6];
    const float* ln2_g  = (const float*)d_in[7];
    const float* ln2_b  = (const float*)d_in[8];
    const float* ffn_w1 = (const float*)d_in[9];
    const float* ffn_b1 = (const float*)d_in[10];
    const float* ffn_w2 = (const float*)d_in[11];
    const float* ffn_b2 = (const float*)d_in[12];
    float* out = (float*)d_out;

    float *x1;
    __half *qkvh, *h16, *att16, *ff16, *wq16, *wo16, *w116, *w216;
    cudaGetSymbolAddress((void**)&x1,   g_x1);
    cudaGetSymbolAddress((void**)&qkvh, g_qkvh);
    cudaGetSymbolAddress((void**)&h16,  g_h16);
    cudaGetSymbolAddress((void**)&att16,g_att16);
    cudaGetSymbolAddress((void**)&ff16, g_ff16);
    cudaGetSymbolAddress((void**)&wq16, g_wq16);
    cudaGetSymbolAddress((void**)&wo16, g_wo16);
    cudaGetSymbolAddress((void**)&w116, g_w116);
    cudaGetSymbolAddress((void**)&w216, g_w216);

    cudaFuncSetAttribute(gemm_h_kernel, cudaFuncAttributeMaxDynamicSharedMemorySize, (int)GEMM_SMEM);

    // 0) all weight conversions fp32->fp16, one launch
    w2h_all_kernel<<<(N4_ALL + 255) / 256, 256>>>(
        (const float4*)qkv_w, (const float4*)out_w, (const float4*)ffn_w1, (const float4*)ffn_w2,
        (__half2*)wq16, (__half2*)wo16, (__half2*)w116, (__half2*)w216);

    // 1) LN1 -> fp16
    ln_kernel<<<NTOK, 256>>>(x, ln1_g, ln1_b, h16);
    // 2) QKV projection (fp16 TC, fp16 out)
    gemm_h_kernel<<<dim3(3 * D_MODEL / 128, NTOK / 128), 256, GEMM_SMEM>>>(
        h16, wq16, qkv_b, nullptr, nullptr, qkvh, NTOK, 3 * D_MODEL, D_MODEL, EPI_BIAS_H);
    // 3) flash windowed attention (fp16 TC)
    attn_flash_kernel<<<dim3(SEQ_L / 64, N_HEADS, BATCH), 256>>>(qkvh, att16);
    // 4) output projection + residual (fp16 TC, fp32 out)
    gemm_h_kernel<<<dim3(D_MODEL / 128, NTOK / 128), 256, GEMM_SMEM>>>(
        att16, wo16, out_b, x, x1, nullptr, NTOK, D_MODEL, D_MODEL, EPI_BIAS_RES);
    // 5) LN2 -> fp16
    ln_kernel<<<NTOK, 256>>>(x1, ln2_g, ln2_b, h16);
    // 6) FFN1 + GELU (fp16 TC, fp16 out)
    gemm_h_kernel<<<dim3(2 * D_MODEL / 128, NTOK / 128), 256, GEMM_SMEM>>>(
        h16, w116, ffn_b1, nullptr, nullptr, ff16, NTOK, 2 * D_MODEL, D_MODEL, EPI_GELU_H);
    // 7) FFN2 + residual -> out (fp16 TC, fp32 out)
    gemm_h_kernel<<<dim3(D_MODEL / 128, NTOK / 128), 256, GEMM_SMEM>>>(
        ff16, w216, ffn_b2, x1, out, nullptr, NTOK, D_MODEL, 2 * D_MODEL, EPI_BIAS_RES);
}